// round 17
// baseline (speedup 1.0000x reference)
#include <cuda_runtime.h>
#include <cfloat>
#include <cstdint>

#define Bz 4
#define NN0 8192
#define NN1 2048
#define NN2 512
#define NN3 128

typedef unsigned long long u64;

__device__ __forceinline__ u64 pack2(float x, float y) {
    u64 r; asm("mov.b64 %0, {%1, %2};" : "=l"(r) : "f"(x), "f"(y)); return r;
}
__device__ __forceinline__ float2 unpack2(u64 v) {
    float2 r; asm("mov.b64 {%0, %1}, %2;" : "=f"(r.x), "=f"(r.y) : "l"(v)); return r;
}
__device__ __forceinline__ u64 ffma2(u64 a, u64 b, u64 c) {
    u64 d; asm("fma.rn.f32x2 %0, %1, %2, %3;" : "=l"(d) : "l"(a), "l"(b), "l"(c)); return d;
}
__device__ __forceinline__ unsigned ordf(float f) {
    unsigned b = __float_as_uint(f);
    return b ^ (((unsigned)((int)b >> 31)) | 0x80000000u);
}
__device__ __forceinline__ float unordf(unsigned m) {
    unsigned b = m ^ ((m & 0x80000000u) ? 0x80000000u : 0xffffffffu);
    return __uint_as_float(b);
}

#define INS3(u, si) do { \
    bool p1 = (u) < m1v; \
    unsigned c1v = p1 ? m1v : (u);  int c1s = p1 ? m1s : (si); \
    m1v = p1 ? (u) : m1v;           m1s = p1 ? (si) : m1s; \
    bool p2 = c1v < m2v; \
    unsigned c2v = p2 ? m2v : c1v;  int c2s = p2 ? m2s : c1s; \
    m2v = p2 ? c1v : m2v;           m2s = p2 ? c1s : m2s; \
    bool p3 = c2v < m3v; \
    m3v = p3 ? c2v : m3v;           m3s = p3 ? c2s : m3s; \
} while(0)

#define FMA16(acc, w, F0, F1, F2, F3) do { \
    acc[0]=ffma2(F0.x,(w),acc[0]); acc[1]=ffma2(F0.y,(w),acc[1]); \
    acc[2]=ffma2(F1.x,(w),acc[2]); acc[3]=ffma2(F1.y,(w),acc[3]); \
    acc[4]=ffma2(F2.x,(w),acc[4]); acc[5]=ffma2(F2.y,(w),acc[5]); \
    acc[6]=ffma2(F3.x,(w),acc[6]); acc[7]=ffma2(F3.y,(w),acc[7]); \
} while(0)

// ---------------- scratch (allocation-free) ----------------
__device__ int   g_idx0[Bz*NN1*16];
__device__ int   g_idx1[Bz*NN2*16];
__device__ int   g_idx2[Bz*NN3*16];
__device__ int   g_uidx0[Bz*NN2*3];
__device__ float g_ud20 [Bz*NN2*3];
__device__ int   g_uidx1[Bz*NN1*3];
__device__ float g_ud21 [Bz*NN1*3];
__device__ int   g_uidx2[Bz*NN0*3];
__device__ float g_ud22 [Bz*NN0*3];
__device__ float g_x1 [Bz*NN1*128];
__device__ float g_x2 [Bz*NN2*256];
__device__ float g_x3 [Bz*NN3*512];
__device__ float g_up0[Bz*NN2*256];
__device__ float g_up1[Bz*NN1*128];
__device__ __align__(16) float g_wdup[2*806656];
__device__ __align__(16) float4 g_pos4[Bz*NN0];

#define OFF_D0W1 0
#define OFF_D0W2 768
#define OFF_D1W1 17152
#define OFF_D1W2 50688
#define OFF_D2W1 116224
#define OFF_D2W2 248832
#define OFF_U0W  510976
#define OFF_U1W  707584
#define OFF_U2W  756736
#define OFF_FW1  773888
#define OFF_FW2  790272
#define W_TOTAL  806656

// ---------------- prep: weight duplication ----------------
__global__ void dup_weights_kernel(const float* __restrict__ s0, const float* __restrict__ s1,
                                   const float* __restrict__ s2, const float* __restrict__ s3,
                                   const float* __restrict__ s4, const float* __restrict__ s5,
                                   const float* __restrict__ s6, const float* __restrict__ s7,
                                   const float* __restrict__ s8, const float* __restrict__ s9,
                                   const float* __restrict__ s10, float* __restrict__ dst) {
    int gid = blockIdx.x*256 + threadIdx.x;
    if (gid >= W_TOTAL) return;
    const int offs[11] = {OFF_D0W1,OFF_D0W2,OFF_D1W1,OFF_D1W2,OFF_D2W1,OFF_D2W2,
                          OFF_U0W,OFF_U1W,OFF_U2W,OFF_FW1,OFF_FW2};
    const float* srcs[11] = {s0,s1,s2,s3,s4,s5,s6,s7,s8,s9,s10};
    int seg = 0;
    #pragma unroll
    for (int i = 1; i < 11; i++) seg = (gid >= offs[i]) ? i : seg;
    float v = srcs[seg][gid - offs[seg]];
    reinterpret_cast<float2*>(dst)[gid] = make_float2(v, v);
}

// ---------------- prep: pos -> (x,y,z,|r|^2) ----------------
__global__ void prep_pos4_kernel(const float* __restrict__ pos, float4* __restrict__ out) {
    int i = blockIdx.x*256 + threadIdx.x;
    float x = pos[3*i+0], y = pos[3*i+1], z = pos[3*i+2];
    float rr = x*x + y*y + z*z;
    out[i] = make_float4(x, y, z, rr);
}

// ---------------- KNN K=16 (validated: CNT=32, NWARP=8) ----------------
template<int CNT, int NWARP>
__global__ void knn16_kernel(const float4* __restrict__ pos4, int Nq, int* __restrict__ oidx,
                             int bofs) {
    __shared__ u64 skey[NWARP*16];
    int b = bofs + blockIdx.y, q = blockIdx.x;
    int lane = threadIdx.x & 31, w = threadIdx.x >> 5;
    const float4* rp = pos4 + (size_t)b*NN0;
    float4 qp = rp[q];
    float qx = qp.x, qy = qp.y, qz = qp.z, qq = qp.w;
    int base = w*CNT*32;

    unsigned ud[CNT];
    unsigned m1v = 0xffffffffu, m2v = 0xffffffffu, m3v = 0xffffffffu;
    int m1s = 0, m2s = 0, m3s = 0;
    #pragma unroll
    for (int i = 0; i < CNT; i++) {
        float4 r4 = rp[base + i*32 + lane];
        float dt = qx*r4.x + qy*r4.y + qz*r4.z;
        float dv = qq + r4.w - 2.0f*dt;
        unsigned u = ordf(dv);
        ud[i] = u;
        INS3(u, i);
    }
    for (int s = 0; s < 16; s++) {
        unsigned mh = __reduce_min_sync(0xffffffffu, m1v);
        unsigned cand = (m1v == mh) ? (unsigned)(m1s*32 + lane) : 0xffffffffu;
        unsigned ml = __reduce_min_sync(0xffffffffu, cand);
        if (lane == 0) skey[w*16 + s] = ((u64)mh << 32) | (unsigned)(base + (int)ml);
        if (cand == ml && m1v == mh) {
            unsigned thr = m1v;
            m1v = m2v; m1s = m2s;
            m2v = m3v; m2s = m3s;
            m3v = 0xffffffffu;
            if (m1v == 0xffffffffu) {   // exhausted buffer: exact rebuild above threshold
                m2v = 0xffffffffu; m3v = 0xffffffffu;
                #pragma unroll
                for (int i = 0; i < CNT; i++) {
                    unsigned u = ud[i];
                    if (u > thr) { INS3(u, i); }
                }
            }
        }
    }
    __syncthreads();
    if (w == 0) {
        u64 head = ~0ull; int ptr = 0;
        if (lane < NWARP) head = skey[lane*16];
        size_t obase = ((size_t)b*Nq + q)*16;
        for (int s = 0; s < 16; s++) {
            unsigned hi = (unsigned)(head >> 32);
            unsigned mh = __reduce_min_sync(0xffffffffu, hi);
            unsigned lo = (hi == mh) ? (unsigned)head : 0xffffffffu;
            unsigned ml = __reduce_min_sync(0xffffffffu, lo);
            if (lane == 0) oidx[obase + s] = (int)ml;
            u64 best = ((u64)mh << 32) | ml;
            if (head == best) {
                ptr++;
                head = (ptr < 16) ? skey[lane*16 + ptr] : ~0ull;
            }
        }
    }
}

// ---------------- KNN K=3, warp variant (validated) ----------------
template<int CNT>
__global__ void knn3_kernel(const float4* __restrict__ pos4, int Nq,
                            int* __restrict__ oidx, float* __restrict__ od2, int bofs) {
    int b = bofs + blockIdx.y;
    int lane = threadIdx.x & 31;
    int q = blockIdx.x*8 + (threadIdx.x >> 5);
    const float4* rp = pos4 + (size_t)b*NN0;
    float4 qp = rp[q];
    float qx = qp.x, qy = qp.y, qz = qp.z, qq = qp.w;

    unsigned m1v = 0xffffffffu, m2v = 0xffffffffu, m3v = 0xffffffffu;
    int m1s = 0, m2s = 0, m3s = 0;
    #pragma unroll 8
    for (int i = 0; i < CNT; i++) {
        float4 r4 = rp[i*32 + lane];
        float dt = qx*r4.x + qy*r4.y + qz*r4.z;
        float dv = qq + r4.w - 2.0f*dt;
        unsigned u = ordf(dv);
        INS3(u, i);
    }
    size_t obase = ((size_t)b*Nq + q)*3;
    #pragma unroll
    for (int s = 0; s < 3; s++) {
        unsigned mh = __reduce_min_sync(0xffffffffu, m1v);
        unsigned cand = (m1v == mh) ? (unsigned)(m1s*32 + lane) : 0xffffffffu;
        unsigned ml = __reduce_min_sync(0xffffffffu, cand);
        if (lane == 0) {
            oidx[obase + s] = (int)ml;
            od2[obase + s]  = fmaxf(unordf(mh), 0.0f);
        }
        if (cand == ml && m1v == mh) {
            m1v = m2v; m1s = m2s;
            m2v = m3v; m2s = m3s;
            m3v = 0xffffffffu;
        }
    }
}

// ---------------- down: gather + 2-layer MLP + max over 16 (one center, j-block=2) ----------------
template<int C_PREV, int C_HID>
__global__ void down_kernel(const float* __restrict__ xprev, const float* __restrict__ pos,
                            const int* __restrict__ idx,
                            const float* __restrict__ W1d, const float* __restrict__ b1,
                            const float* __restrict__ W2d, const float* __restrict__ b2,
                            float* __restrict__ xout, int Nq, int xbs, int bofs) {
    constexpr int CIN = 3 + C_PREV;
    extern __shared__ float sm[];
    float* featT = sm;               // CIN*16
    float* hT    = sm + CIN*16;      // C_HID*16
    __shared__ int nbs[16];
    int b = bofs + blockIdx.y, q = blockIdx.x;
    if (threadIdx.x < 16) nbs[threadIdx.x] = idx[((size_t)b*Nq + q)*16 + threadIdx.x];
    __syncthreads();
    const float* rp = pos + (size_t)b*NN0*3;
    float cx = rp[3*q+0], cy = rp[3*q+1], cz = rp[3*q+2];
    const float* xp = xprev + (size_t)b*xbs;
    for (int e = threadIdx.x; e < 16*CIN; e += blockDim.x) {
        int d = e >> 4, k = e & 15;
        int nb = nbs[k];
        float v;
        if      (d == 0) v = rp[3*nb+0] - cx;
        else if (d == 1) v = rp[3*nb+1] - cy;
        else if (d == 2) v = rp[3*nb+2] - cz;
        else             v = xp[(size_t)nb*C_PREV + (d-3)];
        featT[d*16 + k] = v;
    }
    __syncthreads();
    int j0 = 2*threadIdx.x;
    u64 a0[8], a1[8];
    {
        float2 bb = *reinterpret_cast<const float2*>(&b1[j0]);
        u64 p0 = pack2(bb.x, bb.x), p1 = pack2(bb.y, bb.y);
        #pragma unroll
        for (int i = 0; i < 8; i++) { a0[i] = p0; a1[i] = p1; }
    }
    #pragma unroll 2
    for (int d = 0; d < CIN; d++) {
        ulonglong2 w = *reinterpret_cast<const ulonglong2*>(W1d + 2*(d*C_HID + j0));
        const ulonglong2* f = reinterpret_cast<const ulonglong2*>(featT + d*16);
        ulonglong2 f0 = f[0], f1 = f[1], f2 = f[2], f3 = f[3];
        FMA16(a0, w.x, f0, f1, f2, f3);
        FMA16(a1, w.y, f0, f1, f2, f3);
    }
    {
        float4* h0 = reinterpret_cast<float4*>(hT + (size_t)j0*16);
        float4* h1 = reinterpret_cast<float4*>(hT + (size_t)(j0+1)*16);
        #pragma unroll
        for (int i = 0; i < 4; i++) {
            float2 x0 = unpack2(a0[2*i]), x1 = unpack2(a0[2*i+1]);
            h0[i] = make_float4(fmaxf(x0.x,0.f), fmaxf(x0.y,0.f), fmaxf(x1.x,0.f), fmaxf(x1.y,0.f));
            float2 y0 = unpack2(a1[2*i]), y1 = unpack2(a1[2*i+1]);
            h1[i] = make_float4(fmaxf(y0.x,0.f), fmaxf(y0.y,0.f), fmaxf(y1.x,0.f), fmaxf(y1.y,0.f));
        }
    }
    __syncthreads();
    {
        float2 bb = *reinterpret_cast<const float2*>(&b2[j0]);
        u64 p0 = pack2(bb.x, bb.x), p1 = pack2(bb.y, bb.y);
        #pragma unroll
        for (int i = 0; i < 8; i++) { a0[i] = p0; a1[i] = p1; }
    }
    #pragma unroll 2
    for (int d = 0; d < C_HID; d++) {
        ulonglong2 w = *reinterpret_cast<const ulonglong2*>(W2d + 2*(d*C_HID + j0));
        const ulonglong2* f = reinterpret_cast<const ulonglong2*>(hT + d*16);
        ulonglong2 f0 = f[0], f1 = f[1], f2 = f[2], f3 = f[3];
        FMA16(a0, w.x, f0, f1, f2, f3);
        FMA16(a1, w.y, f0, f1, f2, f3);
    }
    float m0 = -FLT_MAX, m1 = -FLT_MAX;
    #pragma unroll
    for (int i = 0; i < 8; i++) {
        float2 x = unpack2(a0[i]); m0 = fmaxf(m0, fmaxf(x.x, x.y));
        float2 y = unpack2(a1[i]); m1 = fmaxf(m1, fmaxf(y.x, y.y));
    }
    *reinterpret_cast<float2*>(&xout[((size_t)b*Nq + q)*C_HID + j0]) = make_float2(m0, m1);
}

// ---------------- up: 3-NN inverse-distance interp + cat + linear + relu ----------------
template<int C_XC, int C_PRV, int C_OUT>
__global__ void up_kernel(const float* __restrict__ xc, const float* __restrict__ prv,
                          const int* __restrict__ idx, const float* __restrict__ d2,
                          const float* __restrict__ Wd, const float* __restrict__ bias,
                          float* __restrict__ out, int Nq, int Nc, int bofs) {
    constexpr int CIN = C_XC + C_PRV;
    constexpr int QT = 16;
    extern __shared__ float sm[];
    float* featT = sm;
    __shared__ float wsh[QT][3];
    __shared__ int   ish[QT][3];
    int b = bofs + blockIdx.y;
    int q0 = blockIdx.x * QT;
    if (threadIdx.x < QT) {
        int q = q0 + threadIdx.x;
        size_t base = ((size_t)b*Nq + q)*3;
        float w0 = 1.0f/(d2[base+0] + 1e-8f);
        float w1 = 1.0f/(d2[base+1] + 1e-8f);
        float w2 = 1.0f/(d2[base+2] + 1e-8f);
        float s = w0 + w1 + w2;
        wsh[threadIdx.x][0] = w0/s; wsh[threadIdx.x][1] = w1/s; wsh[threadIdx.x][2] = w2/s;
        ish[threadIdx.x][0] = idx[base+0]; ish[threadIdx.x][1] = idx[base+1]; ish[threadIdx.x][2] = idx[base+2];
    }
    __syncthreads();
    const float* xcb = xc + (size_t)b*Nc*C_XC;
    for (int e = threadIdx.x; e < CIN*QT; e += blockDim.x) {
        int d = e >> 4, qq = e & 15;
        float v;
        if (d < C_XC) {
            v = wsh[qq][0]*xcb[(size_t)ish[qq][0]*C_XC + d]
              + wsh[qq][1]*xcb[(size_t)ish[qq][1]*C_XC + d]
              + wsh[qq][2]*xcb[(size_t)ish[qq][2]*C_XC + d];
        } else {
            v = prv[((size_t)b*Nq + q0 + qq)*C_PRV + (d - C_XC)];
        }
        featT[e] = v;
    }
    __syncthreads();
    int j0 = 2*threadIdx.x;
    u64 a0[8], a1[8];
    {
        float2 bb = *reinterpret_cast<const float2*>(&bias[j0]);
        u64 p0 = pack2(bb.x, bb.x), p1 = pack2(bb.y, bb.y);
        #pragma unroll
        for (int i = 0; i < 8; i++) { a0[i] = p0; a1[i] = p1; }
    }
    #pragma unroll 2
    for (int d = 0; d < CIN; d++) {
        ulonglong2 w = *reinterpret_cast<const ulonglong2*>(Wd + 2*(d*C_OUT + j0));
        const ulonglong2* f = reinterpret_cast<const ulonglong2*>(featT + d*QT);
        ulonglong2 f0 = f[0], f1 = f[1], f2 = f[2], f3 = f[3];
        FMA16(a0, w.x, f0, f1, f2, f3);
        FMA16(a1, w.y, f0, f1, f2, f3);
    }
    size_t obase = ((size_t)b*Nq + q0)*C_OUT + j0;
    #pragma unroll
    for (int i = 0; i < 8; i++) {
        float2 x = unpack2(a0[i]), y = unpack2(a1[i]);
        *reinterpret_cast<float2*>(&out[obase + (size_t)(2*i+0)*C_OUT]) =
            make_float2(fmaxf(x.x,0.f), fmaxf(y.x,0.f));
        *reinterpret_cast<float2*>(&out[obase + (size_t)(2*i+1)*C_OUT]) =
            make_float2(fmaxf(x.y,0.f), fmaxf(y.y,0.f));
    }
}

// ---------------- fused: up2 + final MLP (QT=16, 64 threads) ----------------
__global__ void up2_final_kernel(const float* __restrict__ up1,
                                 const float* __restrict__ x0, const float* __restrict__ pos0,
                                 const int* __restrict__ idx, const float* __restrict__ d2,
                                 const float* __restrict__ u2Wd, const float* __restrict__ u2b,
                                 const float* __restrict__ fW1d, const float* __restrict__ fb1,
                                 const float* __restrict__ fW2d, const float* __restrict__ fb2,
                                 float* __restrict__ out, int bofs) {
    constexpr int QT = 16;
    __shared__ float featT[134*QT];
    __shared__ float h1T[128*QT];
    __shared__ float wsh[QT][3];
    __shared__ int   ish[QT][3];
    int b = bofs + blockIdx.y;
    int q0 = blockIdx.x * QT;
    if (threadIdx.x < QT) {
        int q = q0 + threadIdx.x;
        size_t base = ((size_t)b*NN0 + q)*3;
        float w0 = 1.0f/(d2[base+0] + 1e-8f);
        float w1 = 1.0f/(d2[base+1] + 1e-8f);
        float w2 = 1.0f/(d2[base+2] + 1e-8f);
        float s = w0 + w1 + w2;
        wsh[threadIdx.x][0] = w0/s; wsh[threadIdx.x][1] = w1/s; wsh[threadIdx.x][2] = w2/s;
        ish[threadIdx.x][0] = idx[base+0]; ish[threadIdx.x][1] = idx[base+1]; ish[threadIdx.x][2] = idx[base+2];
    }
    __syncthreads();
    const float* xcb = up1 + (size_t)b*NN1*128;
    for (int e = threadIdx.x; e < 134*QT; e += 64) {
        int d = e >> 4, qq = e & 15;
        float v;
        if (d < 128) {
            v = wsh[qq][0]*xcb[(size_t)ish[qq][0]*128 + d]
              + wsh[qq][1]*xcb[(size_t)ish[qq][1]*128 + d]
              + wsh[qq][2]*xcb[(size_t)ish[qq][2]*128 + d];
        } else if (d < 131) {
            v = x0  [((size_t)b*NN0 + q0 + qq)*3 + (d-128)];
        } else {
            v = pos0[((size_t)b*NN0 + q0 + qq)*3 + (d-131)];
        }
        featT[e] = v;
    }
    __syncthreads();
    int j0 = 2*threadIdx.x;
    u64 a0[8], a1[8];

    {
        float2 bb = *reinterpret_cast<const float2*>(&u2b[j0]);
        u64 p0 = pack2(bb.x, bb.x), p1 = pack2(bb.y, bb.y);
        #pragma unroll
        for (int i = 0; i < 8; i++) { a0[i] = p0; a1[i] = p1; }
    }
    #pragma unroll 2
    for (int d = 0; d < 134; d++) {
        ulonglong2 w = *reinterpret_cast<const ulonglong2*>(u2Wd + 2*(d*128 + j0));
        const ulonglong2* f = reinterpret_cast<const ulonglong2*>(featT + d*QT);
        ulonglong2 f0 = f[0], f1 = f[1], f2 = f[2], f3 = f[3];
        FMA16(a0, w.x, f0, f1, f2, f3);
        FMA16(a1, w.y, f0, f1, f2, f3);
    }
    {
        float4* h0 = reinterpret_cast<float4*>(h1T + (size_t)j0*QT);
        float4* h1 = reinterpret_cast<float4*>(h1T + (size_t)(j0+1)*QT);
        #pragma unroll
        for (int i = 0; i < 4; i++) {
            float2 x0v = unpack2(a0[2*i]), x1v = unpack2(a0[2*i+1]);
            h0[i] = make_float4(fmaxf(x0v.x,0.f), fmaxf(x0v.y,0.f), fmaxf(x1v.x,0.f), fmaxf(x1v.y,0.f));
            float2 y0v = unpack2(a1[2*i]), y1v = unpack2(a1[2*i+1]);
            h1[i] = make_float4(fmaxf(y0v.x,0.f), fmaxf(y0v.y,0.f), fmaxf(y1v.x,0.f), fmaxf(y1v.y,0.f));
        }
    }
    __syncthreads();

    {
        float2 bb = *reinterpret_cast<const float2*>(&fb1[j0]);
        u64 p0 = pack2(bb.x, bb.x), p1 = pack2(bb.y, bb.y);
        #pragma unroll
        for (int i = 0; i < 8; i++) { a0[i] = p0; a1[i] = p1; }
    }
    #pragma unroll 2
    for (int d = 0; d < 128; d++) {
        ulonglong2 w = *reinterpret_cast<const ulonglong2*>(fW1d + 2*(d*128 + j0));
        const ulonglong2* f = reinterpret_cast<const ulonglong2*>(h1T + d*QT);
        ulonglong2 f0 = f[0], f1 = f[1], f2 = f[2], f3 = f[3];
        FMA16(a0, w.x, f0, f1, f2, f3);
        FMA16(a1, w.y, f0, f1, f2, f3);
    }
    __syncthreads();
    {
        float4* h0 = reinterpret_cast<float4*>(featT + (size_t)j0*QT);
        float4* h1 = reinterpret_cast<float4*>(featT + (size_t)(j0+1)*QT);
        #pragma unroll
        for (int i = 0; i < 4; i++) {
            float2 x0v = unpack2(a0[2*i]), x1v = unpack2(a0[2*i+1]);
            h0[i] = make_float4(fmaxf(x0v.x,0.f), fmaxf(x0v.y,0.f), fmaxf(x1v.x,0.f), fmaxf(x1v.y,0.f));
            float2 y0v = unpack2(a1[2*i]), y1v = unpack2(a1[2*i+1]);
            h1[i] = make_float4(fmaxf(y0v.x,0.f), fmaxf(y0v.y,0.f), fmaxf(y1v.x,0.f), fmaxf(y1v.y,0.f));
        }
    }
    __syncthreads();

    {
        float2 bb = *reinterpret_cast<const float2*>(&fb2[j0]);
        u64 p0 = pack2(bb.x, bb.x), p1 = pack2(bb.y, bb.y);
        #pragma unroll
        for (int i = 0; i < 8; i++) { a0[i] = p0; a1[i] = p1; }
    }
    #pragma unroll 2
    for (int d = 0; d < 128; d++) {
        ulonglong2 w = *reinterpret_cast<const ulonglong2*>(fW2d + 2*(d*128 + j0));
        const ulonglong2* f = reinterpret_cast<const ulonglong2*>(featT + d*QT);
        ulonglong2 f0 = f[0], f1 = f[1], f2 = f[2], f3 = f[3];
        FMA16(a0, w.x, f0, f1, f2, f3);
        FMA16(a1, w.y, f0, f1, f2, f3);
    }
    size_t obase = ((size_t)b*NN0 + q0)*128 + j0;
    #pragma unroll
    for (int i = 0; i < 8; i++) {
        float2 x = unpack2(a0[i]), y = unpack2(a1[i]);
        *reinterpret_cast<float2*>(&out[obase + (size_t)(2*i+0)*128]) = make_float2(x.x, y.x);
        *reinterpret_cast<float2*>(&out[obase + (size_t)(2*i+1)*128]) = make_float2(x.y, y.y);
    }
}

// ---------------- host launch ----------------
extern "C" void kernel_launch(void* const* d_in, const int* in_sizes, int n_in,
                              void* d_out, int out_size) {
    const float* x    = (const float*)d_in[0];
    const float* pos  = (const float*)d_in[1];
    const float* d0W1 = (const float*)d_in[2];
    const float* d0b1 = (const float*)d_in[3];
    const float* d0W2 = (const float*)d_in[4];
    const float* d0b2 = (const float*)d_in[5];
    const float* d1W1 = (const float*)d_in[6];
    const float* d1b1 = (const float*)d_in[7];
    const float* d1W2 = (const float*)d_in[8];
    const float* d1b2 = (const float*)d_in[9];
    const float* d2W1 = (const float*)d_in[10];
    const float* d2b1 = (const float*)d_in[11];
    const float* d2W2 = (const float*)d_in[12];
    const float* d2b2 = (const float*)d_in[13];
    const float* u0W  = (const float*)d_in[14];
    const float* u0b  = (const float*)d_in[15];
    const float* u1W  = (const float*)d_in[16];
    const float* u1b  = (const float*)d_in[17];
    const float* u2W  = (const float*)d_in[18];
    const float* u2b  = (const float*)d_in[19];
    const float* fW1  = (const float*)d_in[20];
    const float* fb1  = (const float*)d_in[21];
    const float* fW2  = (const float*)d_in[22];
    const float* fb2  = (const float*)d_in[23];
    float* out = (float*)d_out;

    int *idx0, *idx1, *idx2, *uidx0, *uidx1, *uidx2;
    float *ud20, *ud21, *ud22, *x1, *x2, *x3, *up0, *up1, *wd;
    float4* pos4;
    cudaGetSymbolAddress((void**)&idx0,  g_idx0);
    cudaGetSymbolAddress((void**)&idx1,  g_idx1);
    cudaGetSymbolAddress((void**)&idx2,  g_idx2);
    cudaGetSymbolAddress((void**)&uidx0, g_uidx0);
    cudaGetSymbolAddress((void**)&uidx1, g_uidx1);
    cudaGetSymbolAddress((void**)&uidx2, g_uidx2);
    cudaGetSymbolAddress((void**)&ud20,  g_ud20);
    cudaGetSymbolAddress((void**)&ud21,  g_ud21);
    cudaGetSymbolAddress((void**)&ud22,  g_ud22);
    cudaGetSymbolAddress((void**)&x1,    g_x1);
    cudaGetSymbolAddress((void**)&x2,    g_x2);
    cudaGetSymbolAddress((void**)&x3,    g_x3);
    cudaGetSymbolAddress((void**)&up0,   g_up0);
    cudaGetSymbolAddress((void**)&up1,   g_up1);
    cudaGetSymbolAddress((void**)&wd,    g_wdup);
    cudaGetSymbolAddress((void**)&pos4,  g_pos4);

    const float* d0W1d = wd + 2*OFF_D0W1;
    const float* d0W2d = wd + 2*OFF_D0W2;
    const float* d1W1d = wd + 2*OFF_D1W1;
    const float* d1W2d = wd + 2*OFF_D1W2;
    const float* d2W1d = wd + 2*OFF_D2W1;
    const float* d2W2d = wd + 2*OFF_D2W2;
    const float* u0Wd  = wd + 2*OFF_U0W;
    const float* u1Wd  = wd + 2*OFF_U1W;
    const float* u2Wd  = wd + 2*OFF_U2W;
    const float* fW1d  = wd + 2*OFF_FW1;
    const float* fW2d  = wd + 2*OFF_FW2;

    cudaFuncSetAttribute((const void*)down_kernel<256,512>,
                         cudaFuncAttributeMaxDynamicSharedMemorySize, 56*1024);
    cudaFuncSetAttribute((const void*)up_kernel<512,256,256>,
                         cudaFuncAttributeMaxDynamicSharedMemorySize, 50*1024);

    // ---- streams + events: SAME footprint class as the validated R14 (3 created streams) ----
    static cudaStream_t sC[4] = {nullptr,nullptr,nullptr,nullptr};  // sC[0] = default stream
    static cudaEvent_t eW;
    static cudaEvent_t eF[4];
    if (!sC[1]) {
        sC[0] = 0;
        for (int c = 1; c < 4; c++) cudaStreamCreateWithFlags(&sC[c], cudaStreamNonBlocking);
        cudaEventCreateWithFlags(&eW, cudaEventDisableTiming);
        for (int c = 1; c < 4; c++) cudaEventCreateWithFlags(&eF[c], cudaEventDisableTiming);
    }

    // ---- preps on default stream (chains wait on eW, which follows both preps) ----
    prep_pos4_kernel<<<(Bz*NN0)/256, 256>>>(pos, pos4);
    dup_weights_kernel<<<(W_TOTAL+255)/256, 256>>>(
        d0W1,d0W2,d1W1,d1W2,d2W1,d2W2,u0W,u1W,u2W,fW1,fW2, wd);
    cudaEventRecord(eW, 0);
    for (int c = 1; c < 4; c++) cudaStreamWaitEvent(sC[c], eW, 0);

    // ---- 4 independent batch chains, one per stream; knn_i paired just before its MLP ----
    for (int c = 0; c < 4; c++) {
        cudaStream_t st = sC[c];
        knn16_kernel<32,8><<<dim3(NN1,1), 256, 0, st>>>(pos4, NN1, idx0, c);
        down_kernel<3,128><<<dim3(NN1,1), 64, (6*16 + 128*16)*sizeof(float), st>>>(
            x, pos, idx0, d0W1d,d0b1, d0W2d,d0b2, x1, NN1, NN0*3, c);
        knn16_kernel<8,8><<<dim3(NN2,1), 256, 0, st>>>(pos4, NN2, idx1, c);
        down_kernel<128,256><<<dim3(NN2,1), 128, (131*16 + 256*16)*sizeof(float), st>>>(
            x1, pos, idx1, d1W1d,d1b1, d1W2d,d1b2, x2, NN2, NN1*128, c);
        knn16_kernel<2,8><<<dim3(NN3,1), 256, 0, st>>>(pos4, NN3, idx2, c);
        down_kernel<256,512><<<dim3(NN3,1), 256, (259*16 + 512*16)*sizeof(float), st>>>(
            x2, pos, idx2, d2W1d,d2b1, d2W2d,d2b2, x3, NN3, NN2*256, c);
        knn3_kernel<4><<<dim3(NN2/8,1), 256, 0, st>>>(pos4, NN2, uidx0, ud20, c);
        up_kernel<512,256,256><<<dim3(NN2/16,1), 128, 768*16*sizeof(float), st>>>(
            x3, x2, uidx0, ud20, u0Wd, u0b, up0, NN2, NN3, c);
        knn3_kernel<16><<<dim3(NN1/8,1), 256, 0, st>>>(pos4, NN1, uidx1, ud21, c);
        up_kernel<256,128,128><<<dim3(NN1/16,1), 64, 384*16*sizeof(float), st>>>(
            up0, x1, uidx1, ud21, u1Wd, u1b, up1, NN1, NN2, c);
        knn3_kernel<64><<<dim3(NN0/8,1), 256, 0, st>>>(pos4, NN0, uidx2, ud22, c);
        up2_final_kernel<<<dim3(NN0/16,1), 64, 0, st>>>(up1, x, pos, uidx2, ud22,
                                                        u2Wd,u2b, fW1d,fb1, fW2d,fb2, out, c);
        if (c > 0) cudaEventRecord(eF[c], st);
    }
    for (int c = 1; c < 4; c++) cudaStreamWaitEvent(0, eF[c], 0);

    // ---- second tuple element: pos0 passthrough ----
    if (out_size >= Bz*NN0*128 + Bz*NN0*3) {
        cudaMemcpyAsync(out + (size_t)Bz*NN0*128, pos,
                        (size_t)Bz*NN0*3*sizeof(float), cudaMemcpyDeviceToDevice);
    }
}